// round 1
// baseline (speedup 1.0000x reference)
#include <cuda_runtime.h>

#define Bx 64
#define Pz 32
#define ATTR 7
#define Cc 224      // A*P*ATTR
#define Rr 4096
#define NLAB 32

// accumulators: xy, wl, rot, obj, noobj
__device__ double g_acc[5];

__global__ void zero_acc_kernel() {
    if (threadIdx.x < 5) g_acc[threadIdx.x] = 0.0;
}

__device__ __forceinline__ float bce_noobj(float x) {
    // reference: -max(log(1 - sigmoid(x)), -100)
    float conf = 1.0f / (1.0f + expf(-x));
    return -fmaxf(logf(1.0f - conf), -100.0f);
}

__global__ void __launch_bounds__(256) yolo_main_kernel(
    const float* __restrict__ preds, const float* __restrict__ labels)
{
    __shared__ int s_key[32];
    __shared__ float red[8];

    // ---------- Part 1: object-cell terms (blocks 0..63, warp 0) ----------
    if (blockIdx.x < Bx && threadIdx.x < 32) {
        int b = blockIdx.x, t = threadIdx.x;
        const float* lab = labels + (b * NLAB + t) * ATTR;
        float l0 = lab[0], l1 = lab[1], l2 = lab[2], l3 = lab[3],
              l4 = lab[4], l5 = lab[5];

        float ang = l0 + 204.8f;          // + R*CELL_ANGLE/2
        float q   = ang / 0.1f;           // / CELL_ANGLE
        int i = (int)floorf(q);
        i = min(max(i, 0), Rr - 1);
        float dq = l1;                    // / CELL_DEPTH (=1.0)
        int j = (int)floorf(dq);
        j = min(max(j, 0), Pz - 1);

        int key = i * Pz + j;
        s_key[t] = key;
        __syncwarp();
        bool active = true;               // last-write-wins dedup
        for (int u = t + 1; u < 32; u++)
            if (s_key[u] == key) active = false;

        float sxy = 0.f, swl = 0.f, srot = 0.f, sobj = 0.f, scorr = 0.f;
        if (active) {
            const float* pp = preds + ((size_t)b * Cc + (size_t)j * ATTR) * Rr + i;
            float x0 = pp[0 * Rr], x1 = pp[1 * Rr], x2 = pp[2 * Rr],
                  x3 = pp[3 * Rr], x4 = pp[4 * Rr], x5 = pp[5 * Rr],
                  x6 = pp[6 * Rr];

            float tx = q - (float)i;
            float ty = dq - (float)j;
            float sx = 1.f / (1.f + expf(-x0));
            float sy = 1.f / (1.f + expf(-x1));
            sxy = (sx - tx) * (sx - tx) + (sy - ty) * (sy - ty);

            float tw = logf(l2 / 1.6f + 1e-16f);
            float tl = logf(l3 / 3.9f + 1e-16f);
            swl = (x2 - tw) * (x2 - tw) + (x3 - tl) * (x3 - tl);

            float r0 = tanhf(x4), r1 = tanhf(x5);
            srot = (r0 - l4) * (r0 - l4) + (r1 - l5) * (r1 - l5);

            float conf = 1.f / (1.f + expf(-x6));
            sobj  = -fmaxf(logf(conf), -100.0f);
            // this cell was counted as noobj in the dense pass: subtract it
            scorr = fmaxf(logf(1.0f - conf), -100.0f); // == -bce_noobj
        }
        #pragma unroll
        for (int off = 16; off; off >>= 1) {
            sxy   += __shfl_down_sync(0xffffffffu, sxy,   off);
            swl   += __shfl_down_sync(0xffffffffu, swl,   off);
            srot  += __shfl_down_sync(0xffffffffu, srot,  off);
            sobj  += __shfl_down_sync(0xffffffffu, sobj,  off);
            scorr += __shfl_down_sync(0xffffffffu, scorr, off);
        }
        if (t == 0) {
            atomicAdd(&g_acc[0], (double)sxy);
            atomicAdd(&g_acc[1], (double)swl);
            atomicAdd(&g_acc[2], (double)srot);
            atomicAdd(&g_acc[3], (double)sobj);
            atomicAdd(&g_acc[4], (double)scorr);
        }
    }

    // ---------- Part 2: dense noobj BCE over all conf elements ----------
    const int N4 = Bx * Pz * (Rr / 4);    // float4 count = 2,097,152
    const float4* p4 = (const float4*)preds;
    float s = 0.f;
    for (int v = blockIdx.x * blockDim.x + threadIdx.x; v < N4;
         v += gridDim.x * blockDim.x) {
        int r4 = v & 1023;                // Rr/4 = 1024
        int ch = (v >> 10) & 31;          // pp
        int b  = v >> 15;
        float4 d = p4[(size_t)(b * Cc + ch * ATTR + 6) * (Rr / 4) + r4];
        s += bce_noobj(d.x) + bce_noobj(d.y) + bce_noobj(d.z) + bce_noobj(d.w);
    }
    #pragma unroll
    for (int off = 16; off; off >>= 1)
        s += __shfl_down_sync(0xffffffffu, s, off);
    int wid = threadIdx.x >> 5, lid = threadIdx.x & 31;
    if (lid == 0) red[wid] = s;
    __syncthreads();
    if (wid == 0) {
        s = (lid < 8) ? red[lid] : 0.f;
        #pragma unroll
        for (int off = 4; off; off >>= 1)
            s += __shfl_down_sync(0xffffffffu, s, off);
        if (lid == 0) atomicAdd(&g_acc[4], (double)s);
    }
}

__global__ void finalize_kernel(float* __restrict__ out) {
    if (threadIdx.x == 0 && blockIdx.x == 0) {
        float lxy    = (float)g_acc[0];
        float lwl    = (float)g_acc[1];
        float lrot   = (float)g_acc[2];
        float lobj   = (float)g_acc[3];
        float lnoobj = (float)g_acc[4];
        out[0] = 10.0f * lxy + 10.0f * lwl + 20.0f * lrot +
                 20.0f * lobj + 1.0f * lnoobj;
        out[1] = lxy;
        out[2] = lwl;
        out[3] = lrot;
        out[4] = lobj;
        out[5] = lnoobj;
    }
}

extern "C" void kernel_launch(void* const* d_in, const int* in_sizes, int n_in,
                              void* d_out, int out_size) {
    const float* preds  = (const float*)d_in[0];
    const float* labels = (const float*)d_in[1];
    float* out = (float*)d_out;

    zero_acc_kernel<<<1, 32>>>();
    yolo_main_kernel<<<2432, 256>>>(preds, labels);
    finalize_kernel<<<1, 32>>>(out);
}

// round 2
// speedup vs baseline: 1.9125x; 1.9125x over previous
#include <cuda_runtime.h>

#define Bx 64
#define Pz 32
#define ATTR 7
#define Cc 224      // A*P*ATTR
#define Rr 4096
#define NLAB 32
#define GRID 1024
#define TPB 256

// accumulators: xy, wl, rot, obj, noobj   (zero-init at load; reset by last block each call)
__device__ double g_acc[5];
__device__ unsigned int g_done;   // zero-init; reset by last block each call

// -max(log(1 - sigmoid(x)), -100) == softplus(x), numerically stable
__device__ __forceinline__ float softplus_fast(float x) {
    return fmaxf(x, 0.0f) + __logf(1.0f + __expf(-fabsf(x)));
}

__global__ void __launch_bounds__(TPB) yolo_fused_kernel(
    const float* __restrict__ preds, const float* __restrict__ labels,
    float* __restrict__ out)
{
    __shared__ int s_key[32];
    __shared__ float red[TPB / 32];

    // ---------- Part 1: object-cell terms (blocks 0..63, warp 0) ----------
    if (blockIdx.x < Bx && threadIdx.x < 32) {
        int b = blockIdx.x, t = threadIdx.x;
        const float* lab = labels + (b * NLAB + t) * ATTR;
        float l0 = lab[0], l1 = lab[1], l2 = lab[2], l3 = lab[3],
              l4 = lab[4], l5 = lab[5];

        float ang = l0 + 204.8f;          // + R*CELL_ANGLE/2
        float q   = ang / 0.1f;           // / CELL_ANGLE
        int i = (int)floorf(q);
        i = min(max(i, 0), Rr - 1);
        float dq = l1;                    // / CELL_DEPTH (=1.0)
        int j = (int)floorf(dq);
        j = min(max(j, 0), Pz - 1);

        int key = i * Pz + j;
        s_key[t] = key;
        __syncwarp();
        bool active = true;               // last-write-wins dedup
        for (int u = t + 1; u < 32; u++)
            if (s_key[u] == key) active = false;

        float sxy = 0.f, swl = 0.f, srot = 0.f, sobj = 0.f, scorr = 0.f;
        if (active) {
            const float* pp = preds + ((size_t)b * Cc + (size_t)j * ATTR) * Rr + i;
            float x0 = pp[0 * Rr], x1 = pp[1 * Rr], x2 = pp[2 * Rr],
                  x3 = pp[3 * Rr], x4 = pp[4 * Rr], x5 = pp[5 * Rr],
                  x6 = pp[6 * Rr];

            float tx = q - (float)i;
            float ty = dq - (float)j;
            float sx = 1.f / (1.f + expf(-x0));
            float sy = 1.f / (1.f + expf(-x1));
            sxy = (sx - tx) * (sx - tx) + (sy - ty) * (sy - ty);

            float tw = logf(l2 / 1.6f + 1e-16f);
            float tl = logf(l3 / 3.9f + 1e-16f);
            swl = (x2 - tw) * (x2 - tw) + (x3 - tl) * (x3 - tl);

            float r0 = tanhf(x4), r1 = tanhf(x5);
            srot = (r0 - l4) * (r0 - l4) + (r1 - l5) * (r1 - l5);

            float conf = 1.f / (1.f + expf(-x6));
            sobj  = -fmaxf(logf(conf), -100.0f);
            // this cell is counted as noobj in the dense pass: subtract it
            scorr = fmaxf(logf(1.0f - conf), -100.0f);   // == -bce_noobj
        }
        #pragma unroll
        for (int off = 16; off; off >>= 1) {
            sxy   += __shfl_down_sync(0xffffffffu, sxy,   off);
            swl   += __shfl_down_sync(0xffffffffu, swl,   off);
            srot  += __shfl_down_sync(0xffffffffu, srot,  off);
            sobj  += __shfl_down_sync(0xffffffffu, sobj,  off);
            scorr += __shfl_down_sync(0xffffffffu, scorr, off);
        }
        if (t == 0) {
            atomicAdd(&g_acc[0], (double)sxy);
            atomicAdd(&g_acc[1], (double)swl);
            atomicAdd(&g_acc[2], (double)srot);
            atomicAdd(&g_acc[3], (double)sobj);
            atomicAdd(&g_acc[4], (double)scorr);
        }
    }

    // ---------- Part 2: dense noobj BCE over all conf elements ----------
    // 262,144 threads x 8 float4 loads each, stride keeps (r4, ch) fixed and
    // steps the image index by 8 -> all 8 LDG.128 issue back-to-back (MLP=8).
    unsigned tid = blockIdx.x * TPB + threadIdx.x;
    int r4 = tid & 1023;                  // Rr/4 = 1024
    int ch = (tid >> 10) & 31;            // depth bin
    int b0 = tid >> 15;                   // 0..7
    const float4* p4 = (const float4*)preds;
    size_t base = ((size_t)(b0 * Cc + ch * ATTR + 6)) * (Rr / 4) + r4;
    const size_t stride = (size_t)8 * Cc * (Rr / 4);   // 8 images of float4

    float4 d[8];
    #pragma unroll
    for (int k = 0; k < 8; k++) d[k] = p4[base + (size_t)k * stride];

    float s = 0.f;
    #pragma unroll
    for (int k = 0; k < 8; k++) {
        s += softplus_fast(d[k].x) + softplus_fast(d[k].y)
           + softplus_fast(d[k].z) + softplus_fast(d[k].w);
    }

    #pragma unroll
    for (int off = 16; off; off >>= 1)
        s += __shfl_down_sync(0xffffffffu, s, off);
    int wid = threadIdx.x >> 5, lid = threadIdx.x & 31;
    if (lid == 0) red[wid] = s;
    __syncthreads();
    if (wid == 0) {
        s = (lid < TPB / 32) ? red[lid] : 0.f;
        #pragma unroll
        for (int off = 4; off; off >>= 1)
            s += __shfl_down_sync(0xffffffffu, s, off);
        if (lid == 0) atomicAdd(&g_acc[4], (double)s);
    }

    // ---------- Part 3: last block finalizes + resets state ----------
    if (threadIdx.x == 0) {
        __threadfence();
        unsigned prev = atomicAdd(&g_done, 1u);
        if (prev == GRID - 1) {
            __threadfence();
            double a0 = *((volatile double*)&g_acc[0]);
            double a1 = *((volatile double*)&g_acc[1]);
            double a2 = *((volatile double*)&g_acc[2]);
            double a3 = *((volatile double*)&g_acc[3]);
            double a4 = *((volatile double*)&g_acc[4]);
            float lxy = (float)a0, lwl = (float)a1, lrot = (float)a2,
                  lobj = (float)a3, lnoobj = (float)a4;
            out[0] = 10.0f * lxy + 10.0f * lwl + 20.0f * lrot +
                     20.0f * lobj + 1.0f * lnoobj;
            out[1] = lxy;
            out[2] = lwl;
            out[3] = lrot;
            out[4] = lobj;
            out[5] = lnoobj;
            // reset for the next graph replay
            g_acc[0] = 0.0; g_acc[1] = 0.0; g_acc[2] = 0.0;
            g_acc[3] = 0.0; g_acc[4] = 0.0;
            g_done = 0u;
            __threadfence();
        }
    }
}

extern "C" void kernel_launch(void* const* d_in, const int* in_sizes, int n_in,
                              void* d_out, int out_size) {
    const float* preds  = (const float*)d_in[0];
    const float* labels = (const float*)d_in[1];
    float* out = (float*)d_out;

    yolo_fused_kernel<<<GRID, TPB>>>(preds, labels, out);
}

// round 4
// speedup vs baseline: 1.9582x; 1.0239x over previous
#include <cuda_runtime.h>

#define Bx 64
#define Pz 32
#define ATTR 7
#define Cc 224      // A*P*ATTR
#define Rr 4096
#define NLAB 32
#define GRID 1024
#define TPB 256

// accumulators: xy, wl, rot, obj, noobj (zero-init at load; reset by last block each call)
__device__ double g_acc[5];
__device__ unsigned int g_done;

// -max(log(1 - sigmoid(x)), -100) == softplus(x), numerically stable
__device__ __forceinline__ float softplus_fast(float x) {
    return fmaxf(x, 0.0f) + __logf(1.0f + __expf(-fabsf(x)));
}
__device__ __forceinline__ float tanh_approx(float x) {
    float y;
    asm("tanh.approx.f32 %0, %1;" : "=f"(y) : "f"(x));
    return y;
}
__device__ __forceinline__ float sigmoid_fast(float x) {
    return 1.0f / (1.0f + __expf(-x));
}

__global__ void __launch_bounds__(TPB) yolo_fused_kernel(
    const float* __restrict__ preds, const float* __restrict__ labels,
    float* __restrict__ out)
{
    __shared__ int s_key[32];
    __shared__ float red[TPB / 32];

    // ---------- Part 1: object-cell terms (blocks 0..63, warp 0) ----------
    if (blockIdx.x < Bx && threadIdx.x < 32) {
        int b = blockIdx.x, t = threadIdx.x;
        const float* lab = labels + (b * NLAB + t) * ATTR;
        float l0 = lab[0], l1 = lab[1], l2 = lab[2], l3 = lab[3],
              l4 = lab[4], l5 = lab[5];

        float ang = l0 + 204.8f;          // + R*CELL_ANGLE/2
        float q   = ang / 0.1f;           // / CELL_ANGLE
        int i = (int)floorf(q);
        i = min(max(i, 0), Rr - 1);
        float dq = l1;                    // / CELL_DEPTH (=1.0)
        int j = (int)floorf(dq);
        j = min(max(j, 0), Pz - 1);

        int key = i * Pz + j;
        s_key[t] = key;
        __syncwarp();
        bool active = true;               // last-write-wins dedup
        for (int u = t + 1; u < 32; u++)
            if (s_key[u] == key) active = false;

        float sxy = 0.f, swl = 0.f, srot = 0.f, sobj = 0.f, scorr = 0.f;
        if (active) {
            const float* pp = preds + ((size_t)b * Cc + (size_t)j * ATTR) * Rr + i;
            float x0 = pp[0 * Rr], x1 = pp[1 * Rr], x2 = pp[2 * Rr],
                  x3 = pp[3 * Rr], x4 = pp[4 * Rr], x5 = pp[5 * Rr],
                  x6 = pp[6 * Rr];

            float tx = q - (float)i;
            float ty = dq - (float)j;
            float sx = sigmoid_fast(x0);
            float sy = sigmoid_fast(x1);
            sxy = (sx - tx) * (sx - tx) + (sy - ty) * (sy - ty);

            float tw = __logf(l2 * 0.625f + 1e-16f);        // /1.6
            float tl = __logf(l3 * 0.2564102564f + 1e-16f); // /3.9
            swl = (x2 - tw) * (x2 - tw) + (x3 - tl) * (x3 - tl);

            float r0 = tanh_approx(x4), r1 = tanh_approx(x5);
            srot = (r0 - l4) * (r0 - l4) + (r1 - l5) * (r1 - l5);

            // -log(sigmoid(x)) = softplus(-x); log(1-sigmoid(x)) = -softplus(x)
            sobj  = softplus_fast(-x6);
            scorr = -softplus_fast(x6);   // remove this cell from dense noobj sum
        }
        #pragma unroll
        for (int off = 16; off; off >>= 1) {
            sxy   += __shfl_xor_sync(0xffffffffu, sxy,   off);
            swl   += __shfl_xor_sync(0xffffffffu, swl,   off);
            srot  += __shfl_xor_sync(0xffffffffu, srot,  off);
            sobj  += __shfl_xor_sync(0xffffffffu, sobj,  off);
            scorr += __shfl_xor_sync(0xffffffffu, scorr, off);
        }
        if (t == 0) {
            atomicAdd(&g_acc[0], (double)sxy);
            atomicAdd(&g_acc[1], (double)swl);
            atomicAdd(&g_acc[2], (double)srot);
            atomicAdd(&g_acc[3], (double)sobj);
            atomicAdd(&g_acc[4], (double)scorr);
        }
    }

    // ---------- Part 2: dense noobj BCE, row-local mapping ----------
    // Each conf row (b,ch) = 1024 float4 (16KB contiguous). 4 warps per row,
    // each warp streams a contiguous 4KB span via 8 loads strided 512B.
    // All 8 LDG.128 front-batched -> MLP=8, same TLB page, same DRAM rows.
    {
        unsigned tid  = blockIdx.x * TPB + threadIdx.x;
        unsigned gw   = tid >> 5;            // global warp 0..8191
        unsigned lane = tid & 31;
        unsigned row  = gw >> 2;             // 0..2047  (= b*32 + ch)
        unsigned part = gw & 3;
        unsigned b    = row >> 5;
        unsigned ch   = row & 31;
        const float4* p4 = (const float4*)preds;
        const float4* bp = p4 + ((size_t)(b * Cc + ch * ATTR + 6)) * (Rr / 4)
                              + part * 256 + lane;

        float4 d0 = bp[0],   d1 = bp[32],  d2 = bp[64],  d3 = bp[96];
        float4 d4 = bp[128], d5 = bp[160], d6 = bp[192], d7 = bp[224];

        float s0 = softplus_fast(d0.x) + softplus_fast(d0.y)
                 + softplus_fast(d0.z) + softplus_fast(d0.w);
        float s1 = softplus_fast(d1.x) + softplus_fast(d1.y)
                 + softplus_fast(d1.z) + softplus_fast(d1.w);
        float s2 = softplus_fast(d2.x) + softplus_fast(d2.y)
                 + softplus_fast(d2.z) + softplus_fast(d2.w);
        float s3 = softplus_fast(d3.x) + softplus_fast(d3.y)
                 + softplus_fast(d3.z) + softplus_fast(d3.w);
        s0 += softplus_fast(d4.x) + softplus_fast(d4.y)
            + softplus_fast(d4.z) + softplus_fast(d4.w);
        s1 += softplus_fast(d5.x) + softplus_fast(d5.y)
            + softplus_fast(d5.z) + softplus_fast(d5.w);
        s2 += softplus_fast(d6.x) + softplus_fast(d6.y)
            + softplus_fast(d6.z) + softplus_fast(d6.w);
        s3 += softplus_fast(d7.x) + softplus_fast(d7.y)
            + softplus_fast(d7.z) + softplus_fast(d7.w);

        float s = (s0 + s1) + (s2 + s3);
        #pragma unroll
        for (int off = 16; off; off >>= 1)
            s += __shfl_xor_sync(0xffffffffu, s, off);
        int wid = threadIdx.x >> 5, lid = threadIdx.x & 31;
        if (lid == 0) red[wid] = s;
        __syncthreads();
        if (wid == 0) {
            s = (lid < TPB / 32) ? red[lid] : 0.f;
            #pragma unroll
            for (int off = 4; off; off >>= 1)
                s += __shfl_xor_sync(0xffffffffu, s, off);
            if (lid == 0) atomicAdd(&g_acc[4], (double)s);
        }
    }

    // ---------- Part 3: last block finalizes + resets state ----------
    if (threadIdx.x == 0) {
        __threadfence();
        unsigned prev = atomicAdd(&g_done, 1u);
        if (prev == GRID - 1) {
            __threadfence();
            double a0 = *((volatile double*)&g_acc[0]);
            double a1 = *((volatile double*)&g_acc[1]);
            double a2 = *((volatile double*)&g_acc[2]);
            double a3 = *((volatile double*)&g_acc[3]);
            double a4 = *((volatile double*)&g_acc[4]);
            float lxy = (float)a0, lwl = (float)a1, lrot = (float)a2,
                  lobj = (float)a3, lnoobj = (float)a4;
            out[0] = 10.0f * lxy + 10.0f * lwl + 20.0f * lrot +
                     20.0f * lobj + 1.0f * lnoobj;
            out[1] = lxy;
            out[2] = lwl;
            out[3] = lrot;
            out[4] = lobj;
            out[5] = lnoobj;
            g_acc[0] = 0.0; g_acc[1] = 0.0; g_acc[2] = 0.0;
            g_acc[3] = 0.0; g_acc[4] = 0.0;
            g_done = 0u;
            __threadfence();
        }
    }
}

extern "C" void kernel_launch(void* const* d_in, const int* in_sizes, int n_in,
                              void* d_out, int out_size) {
    const float* preds  = (const float*)d_in[0];
    const float* labels = (const float*)d_in[1];
    float* out = (float*)d_out;

    yolo_fused_kernel<<<GRID, TPB>>>(preds, labels, out);
}